// round 1
// baseline (speedup 1.0000x reference)
#include <cuda_runtime.h>
#include <math.h>

#define B_TOT 32768
#define F_TOT 512
#define H_TOT 10

// Scratch (allocation-free): transposed, softplus-scaled W2 and the b2·st sum.
__device__ float g_w2s[H_TOT * F_TOT];
__device__ float g_csum;

__device__ __forceinline__ float tanh_fast(float x) {
    float r;
    asm("tanh.approx.f32 %0, %1;" : "=f"(r) : "f"(x));
    return r;
}

// ---------------------------------------------------------------------------
// Precompute: st = softplus(theta); w2s[h][f] = W2[f][h]*st[f]; csum = sum b2*st
// Also writes nn_theta (second output) to out[B : B+F].
// One block of 512 threads (f = tid).
// ---------------------------------------------------------------------------
__global__ void precompute_kernel(const float* __restrict__ W2,
                                  const float* __restrict__ b2,
                                  const float* __restrict__ theta,
                                  float* __restrict__ out_theta) {
    int f = threadIdx.x;
    float th = theta[f];
    // softplus, accurate: log1p(exp(x)) — theta is tiny positive so this is stable.
    float st = log1pf(expf(th));
    out_theta[f] = st;
#pragma unroll
    for (int h = 0; h < H_TOT; h++) {
        g_w2s[h * F_TOT + f] = W2[f * H_TOT + h] * st;
    }
    // block reduction of b2[f]*st[f]
    __shared__ float red[512];
    red[f] = b2[f] * st;
    __syncthreads();
#pragma unroll
    for (int s = 256; s > 0; s >>= 1) {
        if (f < s) red[f] += red[f + s];
        __syncthreads();
    }
    if (f == 0) g_csum = red[0];
}

// ---------------------------------------------------------------------------
// Main kernel: each warp computes y for 4 batch rows.
// Lane l handles features l, l+32, ..., each with H=10 hidden units.
// (W1,b1) live in smem as float2, [h][f] layout -> conflict-free LDS.
// ---------------------------------------------------------------------------
#define WARPS_PER_BLOCK 8
#define B_PER_WARP 4
#define THREADS (WARPS_PER_BLOCK * 32)
#define B_PER_BLOCK (WARPS_PER_BLOCK * B_PER_WARP)   // 32

__global__ __launch_bounds__(THREADS)
void neural_unilasso_kernel(const float* __restrict__ x,
                            const float* __restrict__ W1,
                            const float* __restrict__ b1,
                            const float* __restrict__ bias,
                            float* __restrict__ y) {
    __shared__ float2 fused[H_TOT * F_TOT];   // 40 KB: {W1, b1} in [h][f] layout

    int tid = threadIdx.x;
    // Cooperative load of W1/b1, transposing (f,h) -> [h][f]
    for (int i = tid; i < F_TOT * H_TOT; i += THREADS) {
        int f = i / H_TOT;
        int h = i - f * H_TOT;
        fused[h * F_TOT + f] = make_float2(W1[i], b1[i]);
    }
    __syncthreads();

    int warp = tid >> 5;
    int lane = tid & 31;
    int b0 = (blockIdx.x * WARPS_PER_BLOCK + warp) * B_PER_WARP;
    const float* xb = x + (size_t)b0 * F_TOT;

    float acc0 = 0.f, acc1 = 0.f, acc2 = 0.f, acc3 = 0.f;

#pragma unroll 1
    for (int k = 0; k < F_TOT; k += 32) {
        int f = k + lane;
        float x0 = __ldg(xb + 0 * F_TOT + f);
        float x1 = __ldg(xb + 1 * F_TOT + f);
        float x2 = __ldg(xb + 2 * F_TOT + f);
        float x3 = __ldg(xb + 3 * F_TOT + f);
#pragma unroll
        for (int h = 0; h < H_TOT; h++) {
            float2 wb = fused[h * F_TOT + f];
            float w2 = __ldg(&g_w2s[h * F_TOT + f]);
            float t0 = tanh_fast(fmaf(x0, wb.x, wb.y));
            float t1 = tanh_fast(fmaf(x1, wb.x, wb.y));
            float t2 = tanh_fast(fmaf(x2, wb.x, wb.y));
            float t3 = tanh_fast(fmaf(x3, wb.x, wb.y));
            acc0 = fmaf(t0, w2, acc0);
            acc1 = fmaf(t1, w2, acc1);
            acc2 = fmaf(t2, w2, acc2);
            acc3 = fmaf(t3, w2, acc3);
        }
    }

    // Butterfly reduce the 4 accumulators across the warp.
#pragma unroll
    for (int off = 16; off > 0; off >>= 1) {
        acc0 += __shfl_xor_sync(0xFFFFFFFFu, acc0, off);
        acc1 += __shfl_xor_sync(0xFFFFFFFFu, acc1, off);
        acc2 += __shfl_xor_sync(0xFFFFFFFFu, acc2, off);
        acc3 += __shfl_xor_sync(0xFFFFFFFFu, acc3, off);
    }

    if (lane < B_PER_WARP) {
        float a = (lane == 0) ? acc0 : (lane == 1) ? acc1 : (lane == 2) ? acc2 : acc3;
        y[b0 + lane] = a + bias[0] + g_csum;
    }
}

// ---------------------------------------------------------------------------
// kernel_launch: inputs in setup_inputs order:
//   0:x (B,F)  1:W1 (F,H)  2:b1 (F,H)  3:W2 (F,H)  4:b2 (F)  5:theta (F)  6:bias (1)
// output: y_pred (B) then nn_theta (F), fp32.
// ---------------------------------------------------------------------------
extern "C" void kernel_launch(void* const* d_in, const int* in_sizes, int n_in,
                              void* d_out, int out_size) {
    const float* x     = (const float*)d_in[0];
    const float* W1    = (const float*)d_in[1];
    const float* b1    = (const float*)d_in[2];
    const float* W2    = (const float*)d_in[3];
    const float* b2    = (const float*)d_in[4];
    const float* theta = (const float*)d_in[5];
    const float* bias  = (const float*)d_in[6];
    float* out = (float*)d_out;

    precompute_kernel<<<1, 512>>>(W2, b2, theta, out + B_TOT);
    neural_unilasso_kernel<<<B_TOT / B_PER_BLOCK, THREADS>>>(x, W1, b1, bias, out);
}

// round 4
// speedup vs baseline: 1.0469x; 1.0469x over previous
#include <cuda_runtime.h>
#include <math.h>

#define B_TOT 32768
#define F_TOT 512
#define H_TOT 10

#define THREADS 512          // 16 warps; warp w covers features [32w, 32w+32)
#define NWARP (THREADS / 32)
#define CHUNK 32             // batches per block
#define NB 4                 // batches per inner group

// Scratch (allocation-free): transposed, softplus-scaled W2 and the b2·st sum.
__device__ float g_w2s[H_TOT * F_TOT];
__device__ float g_csum;

__device__ __forceinline__ float tanh_fast(float x) {
    float r;
    asm("tanh.approx.f32 %0, %1;" : "=f"(r) : "f"(x));
    return r;
}

__device__ __forceinline__ float warp_sum(float v) {
#pragma unroll
    for (int off = 16; off > 0; off >>= 1)
        v += __shfl_xor_sync(0xFFFFFFFFu, v, off);
    return v;
}

// ---------------------------------------------------------------------------
// Precompute: st = softplus(theta); w2s[h][f] = W2[f][h]*st[f]; csum = sum b2*st
// Also writes nn_theta (second output) to out[B : B+F]. One block, f = tid.
// ---------------------------------------------------------------------------
__global__ void precompute_kernel(const float* __restrict__ W2,
                                  const float* __restrict__ b2,
                                  const float* __restrict__ theta,
                                  float* __restrict__ out_theta) {
    int f = threadIdx.x;
    float th = theta[f];
    float st = log1pf(expf(th));      // softplus; theta tiny positive -> stable
    out_theta[f] = st;
#pragma unroll
    for (int h = 0; h < H_TOT; h++) {
        g_w2s[h * F_TOT + f] = W2[f * H_TOT + h] * st;
    }
    __shared__ float red[512];
    red[f] = b2[f] * st;
    __syncthreads();
#pragma unroll
    for (int s = 256; s > 0; s >>= 1) {
        if (f < s) red[f] += red[f + s];
        __syncthreads();
    }
    if (f == 0) g_csum = red[0];
}

// ---------------------------------------------------------------------------
// Main kernel: lane owns ONE feature; all 30 params live in registers.
// Block covers all 512 features, processes CHUNK batches.
// Inner loop: pure LDG(x) + FMA + MUFU.TANH — no LDS/param loads.
// ---------------------------------------------------------------------------
__global__ __launch_bounds__(THREADS)
void neural_unilasso_kernel(const float* __restrict__ x,
                            const float* __restrict__ W1,
                            const float* __restrict__ b1,
                            const float* __restrict__ bias,
                            float* __restrict__ y) {
    __shared__ float part[CHUNK * 17];   // [batch_in_chunk][warp], pad 17 vs bank conflicts
    __shared__ float s_base;

    const int tid  = threadIdx.x;
    const int lane = tid & 31;
    const int warp = tid >> 5;
    const int f    = warp * 32 + lane;

    if (tid == 0) s_base = bias[0] + g_csum;

    // Per-lane parameter registers (one-time load).
    float w1r[H_TOT], b1r[H_TOT], w2r[H_TOT];
#pragma unroll
    for (int h = 0; h < H_TOT; h++) {
        w1r[h] = __ldg(&W1[f * H_TOT + h]);
        b1r[h] = __ldg(&b1[f * H_TOT + h]);
        w2r[h] = __ldg(&g_w2s[h * F_TOT + f]);
    }

    const int bchunk = blockIdx.x * CHUNK;
    const float* xp = x + (size_t)bchunk * F_TOT + f;

#pragma unroll 1
    for (int g = 0; g < CHUNK; g += NB) {
        float x0 = __ldg(xp + (size_t)(g + 0) * F_TOT);
        float x1 = __ldg(xp + (size_t)(g + 1) * F_TOT);
        float x2 = __ldg(xp + (size_t)(g + 2) * F_TOT);
        float x3 = __ldg(xp + (size_t)(g + 3) * F_TOT);
        float a0 = 0.f, a1 = 0.f, a2 = 0.f, a3 = 0.f;
#pragma unroll
        for (int h = 0; h < H_TOT; h++) {
            float t0 = tanh_fast(fmaf(x0, w1r[h], b1r[h]));
            float t1 = tanh_fast(fmaf(x1, w1r[h], b1r[h]));
            float t2 = tanh_fast(fmaf(x2, w1r[h], b1r[h]));
            float t3 = tanh_fast(fmaf(x3, w1r[h], b1r[h]));
            a0 = fmaf(t0, w2r[h], a0);
            a1 = fmaf(t1, w2r[h], a1);
            a2 = fmaf(t2, w2r[h], a2);
            a3 = fmaf(t3, w2r[h], a3);
        }
        a0 = warp_sum(a0);
        a1 = warp_sum(a1);
        a2 = warp_sum(a2);
        a3 = warp_sum(a3);
        if (lane < NB) {
            float v = (lane == 0) ? a0 : (lane == 1) ? a1 : (lane == 2) ? a2 : a3;
            part[(g + lane) * 17 + warp] = v;
        }
    }
    __syncthreads();

    if (tid < CHUNK) {
        float s = s_base;
#pragma unroll
        for (int w = 0; w < NWARP; w++) s += part[tid * 17 + w];
        y[bchunk + tid] = s;
    }
}

// ---------------------------------------------------------------------------
// kernel_launch: inputs in setup_inputs order:
//   0:x (B,F)  1:W1 (F,H)  2:b1 (F,H)  3:W2 (F,H)  4:b2 (F)  5:theta (F)  6:bias (1)
// output: y_pred (B) then nn_theta (F), fp32.
// ---------------------------------------------------------------------------
extern "C" void kernel_launch(void* const* d_in, const int* in_sizes, int n_in,
                              void* d_out, int out_size) {
    const float* x     = (const float*)d_in[0];
    const float* W1    = (const float*)d_in[1];
    const float* b1    = (const float*)d_in[2];
    const float* W2    = (const float*)d_in[3];
    const float* b2    = (const float*)d_in[4];
    const float* theta = (const float*)d_in[5];
    const float* bias  = (const float*)d_in[6];
    float* out = (float*)d_out;

    precompute_kernel<<<1, 512>>>(W2, b2, theta, out + B_TOT);
    neural_unilasso_kernel<<<B_TOT / CHUNK, THREADS>>>(x, W1, b1, bias, out);
}

// round 5
// speedup vs baseline: 1.1250x; 1.0746x over previous
#include <cuda_runtime.h>
#include <cuda_fp16.h>
#include <math.h>

#define B_TOT 32768
#define F_TOT 512
#define H_TOT 10
#define H_F32 4              // h in [0, H_F32) via fp32 tanh; rest via f16x2

#define THREADS 512          // 16 warps; warp w covers features [32w, 32w+32)
#define NWARP (THREADS / 32)
#define CHUNK 32             // batches per block
#define NB 4                 // batches per inner group

__device__ __forceinline__ float tanh_fast(float x) {
    float r;
    asm("tanh.approx.f32 %0, %1;" : "=f"(r) : "f"(x));
    return r;
}

__device__ __forceinline__ __half2 tanh2_fast(__half2 v) {
    unsigned a = *reinterpret_cast<unsigned*>(&v), r;
    asm("tanh.approx.f16x2 %0, %1;" : "=r"(r) : "r"(a));
    return *reinterpret_cast<__half2*>(&r);
}

__device__ __forceinline__ float warp_sum(float v) {
#pragma unroll
    for (int off = 16; off > 0; off >>= 1)
        v += __shfl_xor_sync(0xFFFFFFFFu, v, off);
    return v;
}

// ---------------------------------------------------------------------------
// Single fused kernel. Lane owns one feature f = warp*32+lane; all params in
// registers. Per-block prologue recomputes softplus(theta), w2s, csum (cheap).
// Inner loop: LDG(x, double-buffered) + FFMA + MUFU tanh (fp32 + f16x2 hybrid).
// ---------------------------------------------------------------------------
__global__ __launch_bounds__(THREADS)
void neural_unilasso_kernel(const float* __restrict__ x,
                            const float* __restrict__ W1,
                            const float* __restrict__ b1,
                            const float* __restrict__ W2,
                            const float* __restrict__ b2,
                            const float* __restrict__ theta,
                            const float* __restrict__ bias,
                            float* __restrict__ y,
                            float* __restrict__ y_theta) {
    __shared__ float part[CHUNK * 17];   // [batch][warp], padded stride
    __shared__ float s_red[NWARP];
    __shared__ float s_base;

    const int tid  = threadIdx.x;
    const int lane = tid & 31;
    const int warp = tid >> 5;
    const int f    = warp * 32 + lane;   // THREADS == F_TOT

    // ---- prologue: params + softplus + csum (few hundred cycles) ----
    const float th = theta[f];
    const float st = log1pf(expf(th));           // softplus
    if (blockIdx.x == 0) y_theta[f] = st;        // nn_theta output

    float w1r[H_TOT], b1r[H_TOT], w2r[H_TOT];
#pragma unroll
    for (int h = 0; h < H_TOT; h++) {
        w1r[h] = __ldg(&W1[f * H_TOT + h]);
        b1r[h] = __ldg(&b1[f * H_TOT + h]);
        w2r[h] = __ldg(&W2[f * H_TOT + h]) * st;
    }
    {
        float c = warp_sum(b2[f] * st);
        if (lane == 0) s_red[warp] = c;
        __syncthreads();
        if (tid == 0) {
            float s = bias[0];
#pragma unroll
            for (int w = 0; w < NWARP; w++) s += s_red[w];
            s_base = s;
        }
        __syncthreads();
    }

    const int bchunk = blockIdx.x * CHUNK;
    const float* xp = x + (size_t)bchunk * F_TOT + f;

    // double-buffered x
    float xc0 = __ldg(xp + 0 * F_TOT);
    float xc1 = __ldg(xp + 1 * F_TOT);
    float xc2 = __ldg(xp + 2 * F_TOT);
    float xc3 = __ldg(xp + 3 * F_TOT);

#pragma unroll 1
    for (int g = 0; g < CHUNK; g += NB) {
        float xn0, xn1, xn2, xn3;
        if (g + NB < CHUNK) {
            xn0 = __ldg(xp + (size_t)(g + NB + 0) * F_TOT);
            xn1 = __ldg(xp + (size_t)(g + NB + 1) * F_TOT);
            xn2 = __ldg(xp + (size_t)(g + NB + 2) * F_TOT);
            xn3 = __ldg(xp + (size_t)(g + NB + 3) * F_TOT);
        }

        float a0 = 0.f, a1 = 0.f, a2 = 0.f, a3 = 0.f;
        // fp32 tanh path
#pragma unroll
        for (int h = 0; h < H_F32; h++) {
            float t0 = tanh_fast(fmaf(xc0, w1r[h], b1r[h]));
            float t1 = tanh_fast(fmaf(xc1, w1r[h], b1r[h]));
            float t2 = tanh_fast(fmaf(xc2, w1r[h], b1r[h]));
            float t3 = tanh_fast(fmaf(xc3, w1r[h], b1r[h]));
            a0 = fmaf(t0, w2r[h], a0);
            a1 = fmaf(t1, w2r[h], a1);
            a2 = fmaf(t2, w2r[h], a2);
            a3 = fmaf(t3, w2r[h], a3);
        }
        // f16x2 tanh path: pack batch-pairs, 2 tanh per MUFU op
#pragma unroll
        for (int h = H_F32; h < H_TOT; h++) {
            __half2 p01 = __floats2half2_rn(fmaf(xc0, w1r[h], b1r[h]),
                                            fmaf(xc1, w1r[h], b1r[h]));
            __half2 p23 = __floats2half2_rn(fmaf(xc2, w1r[h], b1r[h]),
                                            fmaf(xc3, w1r[h], b1r[h]));
            __half2 t01 = tanh2_fast(p01);
            __half2 t23 = tanh2_fast(p23);
            a0 = fmaf(__low2float(t01),  w2r[h], a0);
            a1 = fmaf(__high2float(t01), w2r[h], a1);
            a2 = fmaf(__low2float(t23),  w2r[h], a2);
            a3 = fmaf(__high2float(t23), w2r[h], a3);
        }

        // folded 4-accumulator warp reduction (11 SHFL)
        a0 += __shfl_xor_sync(0xFFFFFFFFu, a0, 16);
        a1 += __shfl_xor_sync(0xFFFFFFFFu, a1, 16);
        a2 += __shfl_xor_sync(0xFFFFFFFFu, a2, 16);
        a3 += __shfl_xor_sync(0xFFFFFFFFu, a3, 16);
        a0 += __shfl_xor_sync(0xFFFFFFFFu, a0, 8);
        a1 += __shfl_xor_sync(0xFFFFFFFFu, a1, 8);
        a2 += __shfl_xor_sync(0xFFFFFFFFu, a2, 8);
        a3 += __shfl_xor_sync(0xFFFFFFFFu, a3, 8);
        int q = (lane >> 3) & 3;                 // quarter selects its accumulator
        float c = (q == 0) ? a0 : (q == 1) ? a1 : (q == 2) ? a2 : a3;
        c += __shfl_xor_sync(0xFFFFFFFFu, c, 4);
        c += __shfl_xor_sync(0xFFFFFFFFu, c, 2);
        c += __shfl_xor_sync(0xFFFFFFFFu, c, 1);
        if ((lane & 7) == 0)
            part[(g + q) * 17 + warp] = c;

        xc0 = xn0; xc1 = xn1; xc2 = xn2; xc3 = xn3;
    }
    __syncthreads();

    if (tid < CHUNK) {
        float s = s_base;
#pragma unroll
        for (int w = 0; w < NWARP; w++) s += part[tid * 17 + w];
        y[bchunk + tid] = s;
    }
}

// ---------------------------------------------------------------------------
// kernel_launch: inputs in setup_inputs order:
//   0:x (B,F)  1:W1 (F,H)  2:b1 (F,H)  3:W2 (F,H)  4:b2 (F)  5:theta (F)  6:bias (1)
// output: y_pred (B) then nn_theta (F), fp32.
// ---------------------------------------------------------------------------
extern "C" void kernel_launch(void* const* d_in, const int* in_sizes, int n_in,
                              void* d_out, int out_size) {
    const float* x     = (const float*)d_in[0];
    const float* W1    = (const float*)d_in[1];
    const float* b1    = (const float*)d_in[2];
    const float* W2    = (const float*)d_in[3];
    const float* b2    = (const float*)d_in[4];
    const float* theta = (const float*)d_in[5];
    const float* bias  = (const float*)d_in[6];
    float* out = (float*)d_out;

    neural_unilasso_kernel<<<B_TOT / CHUNK, THREADS>>>(
        x, W1, b1, W2, b2, theta, bias, out, out + B_TOT);
}

// round 6
// speedup vs baseline: 1.1392x; 1.0126x over previous
#include <cuda_runtime.h>
#include <cuda_fp16.h>
#include <math.h>

#define B_TOT 32768
#define F_TOT 512
#define H_TOT 10

#define THREADS 512          // 16 warps; warp w covers features [32w, 32w+32)
#define NWARP (THREADS / 32)
#define CHUNK 32             // batches per block
#define NB 4                 // batches per inner group (2 half2 pairs)

__device__ __forceinline__ __half2 tanh2_fast(__half2 v) {
    unsigned a = *reinterpret_cast<unsigned*>(&v), r;
    asm("tanh.approx.f16x2 %0, %1;" : "=r"(r) : "r"(a));
    return *reinterpret_cast<__half2*>(&r);
}

__device__ __forceinline__ float warp_sum(float v) {
#pragma unroll
    for (int off = 16; off > 0; off >>= 1)
        v += __shfl_xor_sync(0xFFFFFFFFu, v, off);
    return v;
}

// ---------------------------------------------------------------------------
// Single fused kernel. Lane owns one feature f = warp*32+lane; all params in
// registers (W1/b1 broadcast as half2, w2*softplus in fp32). Inner loop per h:
// 2 HFMA2 + 2 MUFU tanh2 + 4 cvt + 4 fp32 FFMA. fp32 accumulation throughout.
// ---------------------------------------------------------------------------
__global__ __launch_bounds__(THREADS)
void neural_unilasso_kernel(const float* __restrict__ x,
                            const float* __restrict__ W1,
                            const float* __restrict__ b1,
                            const float* __restrict__ W2,
                            const float* __restrict__ b2,
                            const float* __restrict__ theta,
                            const float* __restrict__ bias,
                            float* __restrict__ y,
                            float* __restrict__ y_theta) {
    __shared__ float part[CHUNK * 17];   // [batch][warp], padded stride
    __shared__ float s_red[NWARP];
    __shared__ float s_base;

    const int tid  = threadIdx.x;
    const int lane = tid & 31;
    const int warp = tid >> 5;
    const int f    = warp * 32 + lane;   // THREADS == F_TOT

    // ---- prologue: params + softplus + csum ----
    const float th = theta[f];
    const float st = log1pf(expf(th));           // softplus
    if (blockIdx.x == 0) y_theta[f] = st;        // nn_theta output

    __half2 w1h[H_TOT], b1h[H_TOT];
    float w2r[H_TOT];
#pragma unroll
    for (int h = 0; h < H_TOT; h++) {
        float w1 = __ldg(&W1[f * H_TOT + h]);
        float bb = __ldg(&b1[f * H_TOT + h]);
        w1h[h] = __floats2half2_rn(w1, w1);      // broadcast both halves
        b1h[h] = __floats2half2_rn(bb, bb);
        w2r[h] = __ldg(&W2[f * H_TOT + h]) * st; // fp32, exact scaling
    }
    {
        float c = warp_sum(b2[f] * st);
        if (lane == 0) s_red[warp] = c;
        __syncthreads();
        if (tid == 0) {
            float s = bias[0];
#pragma unroll
            for (int w = 0; w < NWARP; w++) s += s_red[w];
            s_base = s;
        }
        __syncthreads();
    }

    const int bchunk = blockIdx.x * CHUNK;
    const float* xp = x + (size_t)bchunk * F_TOT + f;

    // double-buffered x (fp32 loads; packed to half2 per group)
    float xc0 = __ldg(xp + 0 * F_TOT);
    float xc1 = __ldg(xp + 1 * F_TOT);
    float xc2 = __ldg(xp + 2 * F_TOT);
    float xc3 = __ldg(xp + 3 * F_TOT);

#pragma unroll 1
    for (int g = 0; g < CHUNK; g += NB) {
        float xn0, xn1, xn2, xn3;
        if (g + NB < CHUNK) {
            xn0 = __ldg(xp + (size_t)(g + NB + 0) * F_TOT);
            xn1 = __ldg(xp + (size_t)(g + NB + 1) * F_TOT);
            xn2 = __ldg(xp + (size_t)(g + NB + 2) * F_TOT);
            xn3 = __ldg(xp + (size_t)(g + NB + 3) * F_TOT);
        }

        const __half2 x01 = __floats2half2_rn(xc0, xc1);
        const __half2 x23 = __floats2half2_rn(xc2, xc3);

        float a0 = 0.f, a1 = 0.f, a2 = 0.f, a3 = 0.f;
#pragma unroll
        for (int h = 0; h < H_TOT; h++) {
            __half2 p01 = __hfma2(x01, w1h[h], b1h[h]);
            __half2 p23 = __hfma2(x23, w1h[h], b1h[h]);
            __half2 t01 = tanh2_fast(p01);
            __half2 t23 = tanh2_fast(p23);
            float2 f01 = __half22float2(t01);
            float2 f23 = __half22float2(t23);
            a0 = fmaf(f01.x, w2r[h], a0);
            a1 = fmaf(f01.y, w2r[h], a1);
            a2 = fmaf(f23.x, w2r[h], a2);
            a3 = fmaf(f23.y, w2r[h], a3);
        }

        // folded 4-accumulator warp reduction (11 SHFL)
        a0 += __shfl_xor_sync(0xFFFFFFFFu, a0, 16);
        a1 += __shfl_xor_sync(0xFFFFFFFFu, a1, 16);
        a2 += __shfl_xor_sync(0xFFFFFFFFu, a2, 16);
        a3 += __shfl_xor_sync(0xFFFFFFFFu, a3, 16);
        a0 += __shfl_xor_sync(0xFFFFFFFFu, a0, 8);
        a1 += __shfl_xor_sync(0xFFFFFFFFu, a1, 8);
        a2 += __shfl_xor_sync(0xFFFFFFFFu, a2, 8);
        a3 += __shfl_xor_sync(0xFFFFFFFFu, a3, 8);
        int q = (lane >> 3) & 3;                 // quarter selects its accumulator
        float c = (q == 0) ? a0 : (q == 1) ? a1 : (q == 2) ? a2 : a3;
        c += __shfl_xor_sync(0xFFFFFFFFu, c, 4);
        c += __shfl_xor_sync(0xFFFFFFFFu, c, 2);
        c += __shfl_xor_sync(0xFFFFFFFFu, c, 1);
        if ((lane & 7) == 0)
            part[(g + q) * 17 + warp] = c;

        xc0 = xn0; xc1 = xn1; xc2 = xn2; xc3 = xn3;
    }
    __syncthreads();

    if (tid < CHUNK) {
        float s = s_base;
#pragma unroll
        for (int w = 0; w < NWARP; w++) s += part[tid * 17 + w];
        y[bchunk + tid] = s;
    }
}

// ---------------------------------------------------------------------------
// kernel_launch: inputs in setup_inputs order:
//   0:x (B,F)  1:W1 (F,H)  2:b1 (F,H)  3:W2 (F,H)  4:b2 (F)  5:theta (F)  6:bias (1)
// output: y_pred (B) then nn_theta (F), fp32.
// ---------------------------------------------------------------------------
extern "C" void kernel_launch(void* const* d_in, const int* in_sizes, int n_in,
                              void* d_out, int out_size) {
    const float* x     = (const float*)d_in[0];
    const float* W1    = (const float*)d_in[1];
    const float* b1    = (const float*)d_in[2];
    const float* W2    = (const float*)d_in[3];
    const float* b2    = (const float*)d_in[4];
    const float* theta = (const float*)d_in[5];
    const float* bias  = (const float*)d_in[6];
    float* out = (float*)d_out;

    neural_unilasso_kernel<<<B_TOT / CHUNK, THREADS>>>(
        x, W1, b1, W2, b2, theta, bias, out, out + B_TOT);
}